// round 15
// baseline (speedup 1.0000x reference)
#include <cuda_runtime.h>
#include <cuda_bf16.h>

typedef unsigned long long u64;

#define B_     64
#define SEQ_   1534
#define CIN_   21
#define D_     516
#define DP_    544    // g_comb row stride (544*4 = 2176 B = 17*128)
#define NROWS_ 1556   // 21 pad + 1534 + 1 slack
#define NK_    74
#define NBAT_  2      // batches per block
#define NTHR_  258
#define STG_   8      // ring slots (2 groups of 4 rows)

// Precomputed temporal sums: 256 index-combos x DP_ (rows 128B-aligned).
__device__ float g_comb[256 * DP_];

// ---- packed f32x2 helpers (Blackwell) ----
__device__ __forceinline__ u64 fma2(u64 a, u64 b, u64 c) {
    u64 d; asm("fma.rn.f32x2 %0,%1,%2,%3;" : "=l"(d) : "l"(a), "l"(b), "l"(c)); return d;
}
__device__ __forceinline__ u64 add2(u64 a, u64 b) {
    u64 d; asm("add.rn.f32x2 %0,%1,%2;" : "=l"(d) : "l"(a), "l"(b)); return d;
}
__device__ __forceinline__ u64 pk2(float lo, float hi) {
    u64 d; asm("mov.b64 %0,{%1,%2};" : "=l"(d) : "f"(lo), "f"(hi)); return d;
}
__device__ __forceinline__ void cp16(unsigned smem_dst, const void* gsrc) {
    asm volatile("cp.async.cg.shared.global [%0], [%1], 16;"
                 :: "r"(smem_dst), "l"(gsrc));
}
__device__ __forceinline__ void stcs2(float* p, u64 a, u64 b) {
    asm volatile("st.global.cs.v2.b64 [%0], {%1, %2};"
                 :: "l"(p), "l"(a), "l"(b) : "memory");
}

// ---------------------------------------------------------------------------
// comb_k: precompute all 256 temporal-sum rows (128B-aligned stride).
// ---------------------------------------------------------------------------
__global__ __launch_bounds__(129) void comb_k(
    const float* __restrict__ hour, const float* __restrict__ wkd,
    const float* __restrict__ day,  const float* __restrict__ mon)
{
    const int code = blockIdx.x;
    const int ih = code & 3, iw = (code >> 2) & 3, id = (code >> 4) & 3, im = (code >> 6) & 3;
    const float4* h4 = (const float4*)(hour + ih * D_);
    const float4* w4 = (const float4*)(wkd  + iw * D_);
    const float4* d4 = (const float4*)(day  + id * D_);
    const float4* m4 = (const float4*)(mon  + im * D_);
    float4* o4 = (float4*)(g_comb + code * DP_);
    const int g = threadIdx.x;
    float4 a = h4[g], b = w4[g], c = d4[g], d = m4[g];
    float4 r;
    r.x = a.x + b.x + c.x + d.x;
    r.y = a.y + b.y + c.y + d.y;
    r.z = a.z + b.z + c.z + d.z;
    r.w = a.w + b.w + c.w + d.w;
    o4[g] = r;
}

// ---------------------------------------------------------------------------
// Main fused embedding.
//   x:    staged per-block from original (B,SEQ,21) layout (no transpose kernel)
//   pe:   direct loads (rows 16B-aligned), register depth-2 pipeline
//   comb: cp.async ring, groups of 4 rows, LDS 1-ahead inside each group
// ---------------------------------------------------------------------------
__global__ __launch_bounds__(NTHR_, 4) void embed_k(
    const float* __restrict__ x,  const float* __restrict__ kernels,
    const int* __restrict__ xmark, const float* __restrict__ pe,
    float* __restrict__ out)
{
    __shared__ float  xs[NBAT_][NROWS_];     // padded per-batch channel row
    __shared__ u64    ksh[NK_ * 8];          // weights duplicated {w,w}
    __shared__ int    tcodeB[NBAT_][80];     // comb BYTE offsets, padded stride
    __shared__ float4 ring[STG_][NTHR_];     // per-thread 16B comb slots

    const int t  = threadIdx.x;
    const int c  = blockIdx.x;               // 0..20
    const int bg = blockIdx.y;               // 0..31

    // stage x: xs[bl][21 + s] = x[bb, s, c]  (strided 4B gathers, L2-hot)
    #pragma unroll
    for (int bl = 0; bl < NBAT_; ++bl) {
        const float* xsrc = x + ((size_t)(bg * NBAT_ + bl) * SEQ_) * CIN_ + c;
        const float* p = xsrc + (size_t)t * CIN_;
        for (int s = t; s < SEQ_; s += NTHR_) {
            xs[bl][21 + s] = *p;
            p += NTHR_ * CIN_;
        }
        if (t < 22) xs[bl][(t < 21) ? t : (NROWS_ - 1)] = 0.0f;
    }
    for (int i = t; i < NK_ * 8; i += NTHR_) {
        unsigned u = __float_as_uint(kernels[i]);
        ksh[i] = ((u64)u << 32) | (u64)u;
    }
    if (t < NBAT_ * NK_) {
        int bl = t / NK_, n = t - bl * NK_;
        int s  = (n < NK_ - 1) ? n * CIN_ + c : (SEQ_ - 1);
        const int* xm = xmark + ((size_t)(bg * NBAT_ + bl) * SEQ_ + s) * 5;
        int code = (xm[3] & 3) + 4 * (xm[2] & 3) + 16 * (xm[1] & 3) + 64 * (xm[0] & 3);
        tcodeB[bl][n] = code * (DP_ * 4);    // byte offset into g_comb
    }
    __syncthreads();

    const int bl = t / 129;
    const int g  = t - bl * 129;             // 0..128
    const int d0 = 4 * g;
    const int bb = bg * NBAT_ + bl;

    // 17 needed x floats via 5 LDS.128 (base 12g is 16B-aligned)
    float xl[20];
    #pragma unroll
    for (int q = 0; q < 5; q++) {
        float4 v = *(const float4*)&xs[bl][3 * d0 + 4 * q];
        xl[4 * q + 0] = v.x; xl[4 * q + 1] = v.y; xl[4 * q + 2] = v.z; xl[4 * q + 3] = v.w;
    }
    // dedup: chain A uses ax[0..7], chain B uses ax[6..13]
    u64 ax[14];
    #pragma unroll
    for (int k = 0; k < 14; k++) ax[k] = pk2(xl[k], xl[k + 3]);

    const char*  cb    = (const char*)g_comb + (size_t)d0 * 4;   // d0 pre-folded
    float*       out_p = out + ((size_t)bb * SEQ_ + c) * D_ + d0;
    const int*   tcp   = &tcodeB[bl][0];

    const unsigned sp = (unsigned)__cvta_generic_to_shared(&ring[0][t]);
    const unsigned SS = (unsigned)(NTHR_ * sizeof(float4));

    // ---- comb pipeline prologue: groups 0,1 (rows 0..7) ----
    #pragma unroll
    for (int gq = 0; gq < 2; gq++) {
        int4 tc = *(const int4*)&tcp[gq * 4];
        cp16(sp + (gq * 4 + 0) * SS, cb + tc.x);
        cp16(sp + (gq * 4 + 1) * SS, cb + tc.y);
        cp16(sp + (gq * 4 + 2) * SS, cb + tc.z);
        cp16(sp + (gq * 4 + 3) * SS, cb + tc.w);
        asm volatile("cp.async.commit_group;");
    }
    // pe register pipeline: row 0 (pe rows are 16B-aligned: 516*4 = 2064 = 16*129)
    const float* pe_next = pe + (size_t)c * D_ + d0;
    ulonglong2 pp = *(const ulonglong2*)pe_next;
    pe_next += CIN_ * D_;

    auto body = [&](int n, ulonglong2 cc) {
        ulonglong2 ppn = *(const ulonglong2*)pe_next;    // row n+1 pe
        pe_next += CIN_ * D_;

        const ulonglong2* kp = (const ulonglong2*)&ksh[n * 8];
        ulonglong2 k0 = kp[0], k1 = kp[1], k2 = kp[2], k3 = kp[3];

        u64 e0 = add2(pp.x, cc.x);      u64 e1 = add2(pp.y, cc.y);
        u64 a  = fma2(ax[0], k0.x, e0); u64 b2 = fma2(ax[6],  k0.x, e1);
        a = fma2(ax[1], k0.y, a);       b2 = fma2(ax[7],  k0.y, b2);
        a = fma2(ax[2], k1.x, a);       b2 = fma2(ax[8],  k1.x, b2);
        a = fma2(ax[3], k1.y, a);       b2 = fma2(ax[9],  k1.y, b2);
        a = fma2(ax[4], k2.x, a);       b2 = fma2(ax[10], k2.x, b2);
        a = fma2(ax[5], k2.y, a);       b2 = fma2(ax[11], k2.y, b2);
        a = fma2(ax[6], k3.x, a);       b2 = fma2(ax[12], k3.x, b2);
        a = fma2(ax[7], k3.y, a);       b2 = fma2(ax[13], k3.y, b2);

        stcs2(out_p, a, b2);
        out_p += (size_t)CIN_ * D_;
        pp = ppn;
    };

    // ---- main loop: 16 groups x 4 rows = rows 0..63 ----
    #pragma unroll 2
    for (int grp = 0; grp < 16; grp++) {
        asm volatile("cp.async.wait_group 1;");          // group grp ready
        ulonglong2 cc = *(const ulonglong2*)&ring[(grp * 4) & (STG_ - 1)][t];
        #pragma unroll
        for (int j = 0; j < 4; j++) {
            ulonglong2 ccn;
            if (j < 3)
                ccn = *(const ulonglong2*)&ring[(grp * 4 + j + 1) & (STG_ - 1)][t];
            body(grp * 4 + j, cc);
            if (j < 3) cc = ccn;
        }
        // prefetch group grp+2 (rows grp*4+8 .. +11; max row 71 < 73)
        int4 tc = *(const int4*)&tcp[grp * 4 + 8];
        cp16(sp + ((grp * 4 + 8)  & (STG_ - 1)) * SS, cb + tc.x);
        cp16(sp + ((grp * 4 + 9)  & (STG_ - 1)) * SS, cb + tc.y);
        cp16(sp + ((grp * 4 + 10) & (STG_ - 1)) * SS, cb + tc.z);
        cp16(sp + ((grp * 4 + 11) & (STG_ - 1)) * SS, cb + tc.w);
        asm volatile("cp.async.commit_group;");
    }

    // ---- ring tail: rows 64..71 ----
    asm volatile("cp.async.wait_group 0;");
    {
        ulonglong2 cc = *(const ulonglong2*)&ring[64 & (STG_ - 1)][t];
        #pragma unroll
        for (int j = 0; j < 8; j++) {
            ulonglong2 ccn;
            if (j < 7)
                ccn = *(const ulonglong2*)&ring[(64 + j + 1) & (STG_ - 1)][t];
            body(64 + j, cc);
            if (j < 7) cc = ccn;
        }
    }
    // ---- row 72: direct comb load. Clamp pe prefetch to row 1533 (its value
    // is consumed only by the fin row, which exists only at c == 0). ----
    {
        pe_next = pe + (size_t)(SEQ_ - 1) * D_ + d0;
        ulonglong2 cc = *(const ulonglong2*)(cb + tcp[72]);
        body(72, cc);
    }

    // ---- fin row: s = 1533 = 73*21 + 0 -> only channel 0 emits it. ----
    if (c == 0) {
        ulonglong2 cc = *(const ulonglong2*)(cb + tcp[NK_ - 1]);
        const ulonglong2* kp = (const ulonglong2*)&ksh[(NK_ - 1) * 8];
        ulonglong2 k0 = kp[0], k1 = kp[1], k2 = kp[2], k3 = kp[3];
        u64 e0 = add2(pp.x, cc.x);      u64 e1 = add2(pp.y, cc.y);
        u64 a  = fma2(ax[0], k0.x, e0); u64 b2 = fma2(ax[6],  k0.x, e1);
        a = fma2(ax[1], k0.y, a);       b2 = fma2(ax[7],  k0.y, b2);
        a = fma2(ax[2], k1.x, a);       b2 = fma2(ax[8],  k1.x, b2);
        a = fma2(ax[3], k1.y, a);       b2 = fma2(ax[9],  k1.y, b2);
        a = fma2(ax[4], k2.x, a);       b2 = fma2(ax[10], k2.x, b2);
        a = fma2(ax[5], k2.y, a);       b2 = fma2(ax[11], k2.y, b2);
        a = fma2(ax[6], k3.x, a);       b2 = fma2(ax[12], k3.x, b2);
        a = fma2(ax[7], k3.y, a);       b2 = fma2(ax[13], k3.y, b2);
        stcs2(out_p, a, b2);
    }
}

extern "C" void kernel_launch(void* const* d_in, const int* in_sizes, int n_in,
                              void* d_out, int out_size) {
    const float* x    = (const float*)d_in[0];
    const int*   xm   = (const int*)  d_in[1];
    const float* ker  = (const float*)d_in[2];
    const float* pe   = (const float*)d_in[3];
    const float* hour = (const float*)d_in[4];
    const float* wkd  = (const float*)d_in[5];
    const float* day  = (const float*)d_in[6];
    const float* mon  = (const float*)d_in[7];

    comb_k<<<256, 129>>>(hour, wkd, day, mon);
    embed_k<<<dim3(CIN_, B_ / NBAT_), NTHR_>>>(x, ker, xm, pe, (float*)d_out);
}